// round 16
// baseline (speedup 1.0000x reference)
#include <cuda_runtime.h>
#include <cuda_bf16.h>
#include <math.h>

#define B_    16
#define L_    50
#define LU_   60
#define KU_   100
#define DIM_  60
#define V_    2000
#define MAXVL 10
#define MIN_WL 4
#define MAX_WL 10
#define NE_   7
#define INS_DEL 3.5f
#define NEGC  (-9999.9f)
#define LOGP  (-4.60517018598809136804f)  // log(0.01) -> f32

// ---------------- scratch (static device globals) ----------------
__device__ float g_kcr[LU_ * DIM_];          // ku_char_repr [60,60]
__device__ float g_char_lp[LU_ * KU_];       // char_log_probs [60,100]
__device__ float g_pos_lp[B_ * L_ * KU_];    // pos_lp [16,50,100]
__device__ unsigned long long g_best[B_];

__device__ __forceinline__ unsigned orderable(float f) {
    unsigned u = __float_as_uint(f);
    return (u & 0x80000000u) ? ~u : (u | 0x80000000u);
}

// Correctly-rounded f32 log via double (dead axis; any faithful impl ok).
__device__ __forceinline__ float logf_cr(float x) { return (float)log((double)x); }

// XLA:CPU-style Cephes expf (separate fmul/fadd, matching LLVM emission).
__device__ __forceinline__ float xla_expf(float x)
{
    float fx = __fadd_rn(__fmul_rn(x, 1.44269504088896341f), 0.5f);
    fx = floorf(fx);
    float tmp = __fmul_rn(fx, 0.693359375f);
    float z0  = __fmul_rn(fx, -2.12194440e-4f);
    float r   = __fadd_rn(__fadd_rn(x, -tmp), -z0);
    float z   = __fmul_rn(r, r);
    float y = 1.9875691500E-4f;
    y = __fadd_rn(__fmul_rn(y, r), 1.3981999507E-3f);
    y = __fadd_rn(__fmul_rn(y, r), 8.3334519073E-3f);
    y = __fadd_rn(__fmul_rn(y, r), 4.1665795894E-2f);
    y = __fadd_rn(__fmul_rn(y, r), 1.6666665459E-1f);
    y = __fadd_rn(__fmul_rn(y, r), 5.0000001201E-1f);
    y = __fadd_rn(__fmul_rn(y, z), r);
    y = __fadd_rn(y, 1.0f);
    int m = (int)fx;
    float scale = __int_as_float((m + 127) << 23);
    return __fmul_rn(y, scale);
}

// NEON-style 4-lane dot over DIM_=60 contiguous elements:
// acc[lane] strided ascending, then halving tree (a0+a2)+(a1+a3).
__device__ __forceinline__ float dot60_neon(const float* __restrict__ a,
                                            const float* __restrict__ b)
{
    float a0 = 0.f, a1 = 0.f, a2 = 0.f, a3 = 0.f;
    #pragma unroll 5
    for (int c = 0; c < DIM_; c += 4) {
        a0 = fmaf(a[c + 0], b[c + 0], a0);
        a1 = fmaf(a[c + 1], b[c + 1], a1);
        a2 = fmaf(a[c + 2], b[c + 2], a2);
        a3 = fmaf(a[c + 3], b[c + 3], a3);
    }
    float s0 = __fadd_rn(a0, a2);
    float s1 = __fadd_rn(a1, a3);
    return __fadd_rn(s0, s1);
}

// ============ Kernel A1: kcr = aw @ ur, sequential ascending-k ============
// (XLA vectorizes over the contiguous output dim d; per-element k-chain
//  remains sequential — unchanged.)
__global__ void kcr_kernel(const float* __restrict__ aw,  // [LU,KU]
                           const float* __restrict__ ur)  // [KU,DIM]
{
    int lu = blockIdx.x;
    int d  = threadIdx.x;
    if (blockIdx.x == 0 && d < B_) g_best[d] = 0ULL;
    if (d < DIM_) {
        float acc = 0.f;
        for (int k = 0; k < KU_; k++)
            acc = fmaf(aw[lu * KU_ + k], ur[k * DIM_ + d], acc);
        g_kcr[lu * DIM_ + d] = acc;
    }
}

// ============ Kernel A2: char logits (4-lane dot) + log_softmax ============
__global__ void char_kernel(const float* __restrict__ ur,   // [KU,DIM]
                            float* __restrict__ out_align)  // [LU,KU]
{
    int lu  = blockIdx.x;
    int tid = threadIdx.x;   // 128
    __shared__ float logits[KU_];
    __shared__ float mx_s, lse_s;

    if (tid < KU_)
        logits[tid] = dot60_neon(&g_kcr[lu * DIM_], &ur[tid * DIM_]);
    __syncthreads();
    if (tid == 0) {
        float mx = logits[0];
        for (int k = 1; k < KU_; k++) mx = fmaxf(mx, logits[k]);
        float sum = 0.f;
        for (int k = 0; k < KU_; k++)
            sum = __fadd_rn(sum, xla_expf(__fadd_rn(logits[k], -mx)));
        mx_s = mx; lse_s = logf_cr(sum);
    }
    __syncthreads();
    if (tid < KU_) {
        float shifted = __fadd_rn(logits[tid], -mx_s);
        float lp = __fadd_rn(shifted, -lse_s);
        g_char_lp[lu * KU_ + tid] = lp;
        out_align[lu * KU_ + tid] = xla_expf(lp);
    }
}

// ============ Kernel B: conv + ctx log-softmax (4-lane dot) -> pos_lp ======
__global__ void poslp_kernel(const int*   __restrict__ ids, // [B,L]
                             const float* __restrict__ ur,  // [KU,DIM]
                             const float* __restrict__ cw,  // [DIM,DIM,3] (O,I,H)
                             const float* __restrict__ cb)  // [DIM]
{
    int bl = blockIdx.x;
    int b = bl / L_, l = bl % L_;
    int tid = threadIdx.x;   // 128
    __shared__ float word[DIM_];
    __shared__ float logits[KU_];
    __shared__ float mx_s, lse_s;
    __shared__ int   sids[3];

    if (tid < 3) {
        int p = l + tid - 1;
        sids[tid] = (p >= 0 && p < L_) ? ids[b * L_ + p] : -1;
    }
    __syncthreads();

    if (tid < DIM_) {
        // channel-outer / tap-inner ascending FMA chain (consensus form).
        float acc = 0.f;
        const float* w = cw + tid * DIM_ * 3;
        int i0 = sids[0], i1 = sids[1], i2 = sids[2];
        for (int i = 0; i < DIM_; i++) {
            float x0 = (i0 >= 0) ? g_kcr[i0 * DIM_ + i] : 0.f;
            float x1 = (i1 >= 0) ? g_kcr[i1 * DIM_ + i] : 0.f;
            float x2 = (i2 >= 0) ? g_kcr[i2 * DIM_ + i] : 0.f;
            acc = fmaf(w[i * 3 + 0], x0, acc);
            acc = fmaf(w[i * 3 + 1], x1, acc);
            acc = fmaf(w[i * 3 + 2], x2, acc);
        }
        word[tid] = __fadd_rn(acc, cb[tid]);   // bias: separate f32 add
    }
    __syncthreads();
    if (tid < KU_)
        logits[tid] = dot60_neon(word, &ur[tid * DIM_]);
    __syncthreads();
    if (tid == 0) {
        float mx = logits[0];
        for (int k = 1; k < KU_; k++) mx = fmaxf(mx, logits[k]);
        float sum = 0.f;
        for (int k = 0; k < KU_; k++)
            sum = __fadd_rn(sum, xla_expf(__fadd_rn(logits[k], -mx)));
        mx_s = mx; lse_s = logf_cr(sum);
    }
    __syncthreads();
    if (tid < KU_) {
        float shifted = __fadd_rn(logits[tid], -mx_s);
        float ctx_lp  = __fadd_rn(shifted, -lse_s);
        int id0 = ids[b * L_ + l];
        g_pos_lp[(b * L_ + l) * KU_ + tid] =
            __fadd_rn(g_char_lp[id0 * KU_ + tid], __fmul_rn(0.1f, ctx_lp));
    }
}

// ============ Kernel D: DP + per-batch argmax (pruned; proven == literal) ===
__global__ void __launch_bounds__(256) dp_kernel(const int* __restrict__ vids, // [V,MAXVL]
                                                 const int* __restrict__ vls,  // [V]
                                                 const int* __restrict__ lens) // [B]
{
    const int b  = blockIdx.z;
    const int l  = blockIdx.y;
    const int vc = blockIdx.x;
    const int len_b = lens[b];
    if (l + MIN_WL > len_b) return;

    __shared__ float spl[MAX_WL * KU_];
    const int imax = min(MAX_WL, len_b - l);
    const int tot  = imax * KU_;
    const float* src = &g_pos_lp[(b * L_ + l) * KU_];
    for (int i = threadIdx.x; i < tot; i += 256) spl[i] = src[i];
    __syncthreads();

    unsigned long long packed = 0ULL;
    const int v = vc * 256 + threadIdx.x;
    if (v < V_) {
        int vid[MAXVL];
        #pragma unroll
        for (int j = 0; j < MAXVL; j++) vid[j] = vids[v * MAXVL + j];
        const int vl = vls[v];

        float prev[MAXVL + 1];
        #pragma unroll
        for (int j = 0; j <= MAXVL; j++) prev[j] = -INS_DEL * (float)j;

        #pragma unroll
        for (int i = 1; i <= MAX_WL; i++) {
            if (i > imax) break;
            const float* srow = &spl[(i - 1) * KU_];
            float d   = prev[0];
            float cur = -INS_DEL * (float)i;
            prev[0] = cur;
            float llv = cur;
            #pragma unroll
            for (int j = 1; j <= MAXVL; j++) {
                float t = prev[j];
                float s = srow[vid[j - 1]];
                float diag = __fadd_rn(d, s);
                float up   = __fadd_rn(t,   -INS_DEL);
                float left = __fadd_rn(cur, -INS_DEL);
                cur = fmaxf(diag, fmaxf(up, left));
                prev[j] = cur;
                d = t;
                if (j == vl) llv = cur;
            }
            if (i >= MIN_WL) {
                float score = __fadd_rn(llv, __fmul_rn((float)(len_b - i), LOGP));
                unsigned idx = (unsigned)(l * (NE_ * V_) + (i - MIN_WL) * V_ + v);
                unsigned long long p =
                    ((unsigned long long)orderable(score) << 32) | (unsigned)(~idx);
                if (p > packed) packed = p;
            }
        }
    }

    __shared__ unsigned long long sred[256];
    sred[threadIdx.x] = packed;
    __syncthreads();
    for (int s = 128; s > 0; s >>= 1) {
        if (threadIdx.x < s) {
            unsigned long long o = sred[threadIdx.x + s];
            if (o > sred[threadIdx.x]) sred[threadIdx.x] = o;
        }
        __syncthreads();
    }
    if (threadIdx.x == 0) atomicMax(&g_best[b], sred[0]);
}

// ============ Kernel E: decode argmax -> outputs ============
__global__ void final_kernel(float* __restrict__ out)
{
    int b = threadIdx.x;
    if (b < B_) {
        unsigned long long p = g_best[b];
        unsigned ub  = (unsigned)(p >> 32);
        unsigned idx = ~((unsigned)(p & 0xffffffffULL));
        unsigned bits = (ub & 0x80000000u) ? (ub ^ 0x80000000u) : ~ub;
        float score = __uint_as_float(bits);
        int start = idx / (NE_ * V_);
        int e     = (idx / V_) % NE_;
        int vocab = idx % V_;
        int end   = start + MIN_WL + e - 1;
        out[0 * B_ + b] = (float)start;
        out[1 * B_ + b] = (float)end;
        out[2 * B_ + b] = score;
        out[3 * B_ + b] = (float)vocab;
    }
}

// ---------------- launch ----------------
extern "C" void kernel_launch(void* const* d_in, const int* in_sizes, int n_in,
                              void* d_out, int out_size)
{
    const int*   ids  = (const int*)  d_in[0];
    const int*   lens = (const int*)  d_in[1];
    const float* ur   = (const float*)d_in[2];
    const float* aw   = (const float*)d_in[3];
    const float* cw   = (const float*)d_in[4];
    const float* cb   = (const float*)d_in[5];
    const int*   vids = (const int*)  d_in[6];
    const int*   vls  = (const int*)  d_in[7];
    float* out = (float*)d_out;   // [start16|end16|ll16|vocab16|align6000]

    kcr_kernel <<<LU_, 64>>>(aw, ur);
    char_kernel<<<LU_, 128>>>(ur, out + 4 * B_);
    poslp_kernel<<<B_ * L_, 128>>>(ids, ur, cw, cb);
    dim3 g((V_ + 255) / 256, L_, B_);
    dp_kernel<<<g, 256>>>(vids, vls, lens);
    final_kernel<<<1, 32>>>(out);
}